// round 10
// baseline (speedup 1.0000x reference)
#include <cuda_runtime.h>
#include <cuda_bf16.h>

#define M_NODES 10000
#define T_STEPS 40
#define KNN     16
#define FSEM    32
#define EPSV    1e-8f

// One 64B record per (tt, j): a = (pref.xyz, 1/(2sig^2+eps)); b = q_rel; c = (p_live.xyz, 0).
// 64B alignment => record never straddles a 128B line; the 3 gathers per neighbor
// hit one line (1 L1 miss + 2 hits) and pull 2 L2 sectors instead of 3.
struct __align__(64) NodeRec { float4 a, b, c, pad; };
__device__ NodeRec g_R[T_STEPS * M_NODES];   // 25.6 MB, L2-resident

struct Quat { float w, x, y, z; };

__device__ __forceinline__ Quat qnormalize(Quat q) {
    float n2 = q.w * q.w + q.x * q.x + q.y * q.y + q.z * q.z;
    float inv = rsqrtf(fmaxf(n2, 1e-24f));   // matches reference clip(norm,1e-12)
    Quat r; r.w = q.w * inv; r.x = q.x * inv; r.y = q.y * inv; r.z = q.z * inv;
    return r;
}

__device__ __forceinline__ Quat qload(float4 v) {
    Quat q; q.w = v.x; q.x = v.y; q.y = v.z; q.z = v.w; return q;
}

__device__ __forceinline__ Quat qmul(Quat a, Quat b) {
    Quat r;
    r.w = a.w * b.w - a.x * b.x - a.y * b.y - a.z * b.z;
    r.x = a.w * b.x + a.x * b.w + a.y * b.z - a.z * b.y;
    r.y = a.w * b.y - a.x * b.z + a.y * b.w + a.z * b.x;
    r.z = a.w * b.z + a.x * b.y - a.y * b.x + a.z * b.w;
    return r;
}

// RAW q2R (no internal normalize): for q ~ 0 yields ~I (reference degenerate path).
__device__ __forceinline__ void q2R(Quat q, float R[3][3]) {
    float w = q.w, x = q.x, y = q.y, z = q.z;
    R[0][0] = 1.f - 2.f * (y * y + z * z);
    R[0][1] = 2.f * (x * y - w * z);
    R[0][2] = 2.f * (x * z + w * y);
    R[1][0] = 2.f * (x * y + w * z);
    R[1][1] = 1.f - 2.f * (x * x + z * z);
    R[1][2] = 2.f * (y * z - w * x);
    R[2][0] = 2.f * (x * z - w * y);
    R[2][1] = 2.f * (y * z + w * x);
    R[2][2] = 1.f - 2.f * (x * x + y * y);
}

__device__ __forceinline__ void mat3mul(const float A[3][3], const float B[3][3], float C[3][3]) {
    #pragma unroll
    for (int i = 0; i < 3; i++)
        #pragma unroll
        for (int j = 0; j < 3; j++)
            C[i][j] = A[i][0] * B[0][j] + A[i][1] * B[1][j] + A[i][2] * B[2][j];
}

__device__ __forceinline__ float3 qrot(Quat q, float3 v) {
    float tx = 2.f * (q.y * v.z - q.z * v.y);
    float ty = 2.f * (q.z * v.x - q.x * v.z);
    float tz = 2.f * (q.x * v.y - q.y * v.x);
    float3 r;
    r.x = v.x + q.w * tx + (q.y * tz - q.z * ty);
    r.y = v.y + q.w * ty + (q.z * tx - q.x * tz);
    r.z = v.z + q.w * tz + (q.x * ty - q.y * tx);
    return r;
}

__device__ __forceinline__ float sigmoidf(float x) {
    return 1.f / (1.f + __expf(-x));
}

__device__ __forceinline__ float qw_sum(float v) {
    v += __shfl_xor_sync(0xffffffffu, v, 4);
    v += __shfl_xor_sync(0xffffffffu, v, 2);
    v += __shfl_xor_sync(0xffffffffu, v, 1);
    return v;
}

// ---- precompute kernel: one thread per (tt, j); builds merged records ----
__global__ void __launch_bounds__(256)
dyn_scf_pre_kernel(
    const float*  __restrict__ node_xyz,
    const float4* __restrict__ node_quat,
    const float*  __restrict__ node_sigma,
    const int*    __restrict__ t_ptr)
{
    int idx = blockIdx.x * blockDim.x + threadIdx.x;
    if (idx >= T_STEPS * M_NODES) return;
    int j = idx % M_NODES;
    int t = __ldg(t_ptr);
    long tMj = (long)t * M_NODES + j;

    Quat qr = qnormalize(qload(__ldg(&node_quat[idx])));
    Quat ql = qnormalize(qload(__ldg(&node_quat[tMj])));
    // q_rel = ql * conj(qr)
    float4 B;
    B.x =  ql.w * qr.w + ql.x * qr.x + ql.y * qr.y + ql.z * qr.z;
    B.y = -ql.w * qr.x + ql.x * qr.w - ql.y * qr.z + ql.z * qr.y;
    B.z = -ql.w * qr.y + ql.x * qr.z + ql.y * qr.w - ql.z * qr.x;
    B.w = -ql.w * qr.z - ql.x * qr.y + ql.y * qr.x + ql.z * qr.w;

    float sig = __ldg(&node_sigma[j]);
    float4 A = make_float4(__ldg(&node_xyz[3L * idx]),
                           __ldg(&node_xyz[3L * idx + 1]),
                           __ldg(&node_xyz[3L * idx + 2]),
                           1.f / (2.f * sig * sig + EPSV));
    float4 C = make_float4(__ldg(&node_xyz[3L * tMj]),
                           __ldg(&node_xyz[3L * tMj + 1]),
                           __ldg(&node_xyz[3L * tMj + 2]), 0.f);

    g_R[idx].a = A;
    g_R[idx].b = B;
    g_R[idx].c = C;
}

// ---- main kernel: quarter-warp (8 lanes) per gaussian; 4 gaussians per warp ----
__global__ void __launch_bounds__(256)
dyn_scf_qw_kernel(
    const float*  __restrict__ gs_xyz,     // (N,3)
    const float4* __restrict__ gs_rot,     // (N,4)
    const float4* __restrict__ node_quat,  // (T,M,4)
    const float4* __restrict__ node_sem4,  // (M,32) as M x 8 float4
    const int*    __restrict__ attach,     // (N,)
    const int*    __restrict__ ref_time,   // (N,)
    const int2*   __restrict__ topo2,      // (M,K) as M x 8 int2
    float*        __restrict__ out,
    int N)
{
    const int lane = threadIdx.x & 31;
    const int kl   = lane & 7;
    const int grp  = (lane >> 3) & 3;
    const long warp_gid = (long)blockIdx.x * (blockDim.x >> 5) + (threadIdx.x >> 5);
    const int n = (int)(warp_gid * 4 + grp);
    if (n >= N) return;   // N % 32 == 0 -> warps never partial

    const int a  = __ldg(&attach[n]);
    const int rt = __ldg(&ref_time[n]);
    const long rtM = (long)rt * M_NODES;

    // topo: one coalesced int2 per lane covers k = 2kl, 2kl+1 (sum order irrelevant)
    const int2 jj = __ldg(&topo2[a * (KNN / 2) + kl]);
    const int j0 = jj.x, j1 = jj.y;

    // ---- preamble: quaternion-only ----
    const NodeRec* Ra = &g_R[rtM + a];
    float4 Aa = __ldg(&Ra->a);
    Quat qa = qnormalize(qload(__ldg(&node_quat[rtM + a])));
    Quat qg = qnormalize(qload(__ldg(&gs_rot[n])));

    float3 gx = { __ldg(&gs_xyz[3 * n]), __ldg(&gs_xyz[3 * n + 1]), __ldg(&gs_xyz[3 * n + 2]) };
    float3 xr = qrot(qa, gx);
    float3 xw = { xr.x + Aa.x, xr.y + Aa.y, xr.z + Aa.z };

    Quat qag = qmul(qa, qg);   // unit*unit -> unit; R_world = R(qag)

    // ---- k-phase gathers: 3 loads per neighbor, all within ONE 128B line ----
    const NodeRec* R0 = &g_R[rtM + j0];
    const NodeRec* R1 = &g_R[rtM + j1];
    float4 A0 = __ldg(&R0->a);
    float4 A1 = __ldg(&R1->a);
    float4 B0 = __ldg(&R0->b);
    float4 B1 = __ldg(&R1->b);
    float4 C0 = __ldg(&R0->c);
    float4 C1 = __ldg(&R1->c);

    float3 d0 = { xw.x - A0.x, xw.y - A0.y, xw.z - A0.z };
    float3 d1 = { xw.x - A1.x, xw.y - A1.y, xw.z - A1.z };
    float w0 = __expf(-(d0.x * d0.x + d0.y * d0.y + d0.z * d0.z) * A0.w);
    float w1 = __expf(-(d1.x * d1.x + d1.y * d1.y + d1.z * d1.z) * A1.w);

    Quat q0; q0.w = B0.x; q0.x = B0.y; q0.y = B0.z; q0.z = B0.w;
    Quat q1; q1.w = B1.x; q1.x = B1.y; q1.y = B1.z; q1.z = B1.w;

    // ---- sem blend FIRST: its 16 loads depend only on (w, j), so they issue
    // before/overlap the reduction shuffle chain below. Interleaved halves for MLP.
    const int src_base = lane & 24;
    float4 sacc = make_float4(0.f, 0.f, 0.f, 0.f);
    #pragma unroll
    for (int k = 0; k < 8; k++) {
        float wk0 = __shfl_sync(0xffffffffu, w0, src_base | k);
        int   jk0 = __shfl_sync(0xffffffffu, j0, src_base | k);
        float wk1 = __shfl_sync(0xffffffffu, w1, src_base | k);
        int   jk1 = __shfl_sync(0xffffffffu, j1, src_base | k);
        float4 v0 = __ldg(&node_sem4[(long)jk0 * (FSEM / 4) + kl]);
        float4 v1 = __ldg(&node_sem4[(long)jk1 * (FSEM / 4) + kl]);
        sacc.x += wk0 * v0.x + wk1 * v1.x;
        sacc.y += wk0 * v0.y + wk1 * v1.y;
        sacc.z += wk0 * v0.z + wk1 * v1.z;
        sacc.w += wk0 * v0.w + wk1 * v1.w;
    }

    float3 m0 = qrot(q0, d0);
    float3 m1 = qrot(q1, d1);

    // ---- group reductions (serve all 4 gaussians of the warp at once) ----
    float S   = qw_sum(w0 + w1);
    float mux = qw_sum(w0 * (m0.x + C0.x) + w1 * (m1.x + C1.x));
    float muy = qw_sum(w0 * (m0.y + C0.y) + w1 * (m1.y + C1.y));
    float muz = qw_sum(w0 * (m0.z + C0.z) + w1 * (m1.z + C1.z));
    float qbw = qw_sum(w0 * q0.w + w1 * q1.w);
    float qbx = qw_sum(w0 * q0.x + w1 * q1.x);
    float qby = qw_sum(w0 * q0.y + w1 * q1.y);
    float qbz = qw_sum(w0 * q0.z + w1 * q1.z);

    float invS = 1.f / (S + EPSV);

    // ---- frame epilogue: EXPLICIT Rb @ Rw (clip-safe; see R8 failure).
    // invS scaling BEFORE normalize is load-bearing (R2 failure): for clipped rows
    // qbn ~ 0 -> Rb ~ I -> Fr = Rw, which quaternion composition would NOT give.
    Quat qbn; qbn.w = qbw * invS; qbn.x = qbx * invS; qbn.y = qby * invS; qbn.z = qbz * invS;
    qbn = qnormalize(qbn);
    float Rb[3][3]; q2R(qbn, Rb);
    float Rw[3][3]; q2R(qag, Rw);
    float Fr[3][3]; mat3mul(Rb, Rw, Fr);

    // ---- outputs ----
    float*  o_mu  = out;
    float*  o_fr  = out + 3L  * N;
    float4* o_sem = (float4*)(out + 28L * N);

    float muv = (kl == 0) ? mux : ((kl == 1) ? muy : muz);
    if (kl < 3) o_mu[3 * n + kl] = muv * invS;

    float frv = Fr[0][0];
    frv = (kl == 1) ? Fr[0][1] : frv;
    frv = (kl == 2) ? Fr[0][2] : frv;
    frv = (kl == 3) ? Fr[1][0] : frv;
    frv = (kl == 4) ? Fr[1][1] : frv;
    frv = (kl == 5) ? Fr[1][2] : frv;
    frv = (kl == 6) ? Fr[2][0] : frv;
    frv = (kl == 7) ? Fr[2][1] : frv;
    o_fr[9 * n + kl] = frv;
    if (kl == 0) o_fr[9 * n + 8] = Fr[2][2];

    float4 sv; sv.x = sacc.x * invS; sv.y = sacc.y * invS;
    sv.z = sacc.z * invS; sv.w = sacc.w * invS;
    o_sem[(long)n * (FSEM / 4) + kl] = sv;
}

// ---- elementwise outputs: s, o, sph — float4 vectorized ----
__global__ void __launch_bounds__(256)
dyn_scf_elem_kernel(
    const float4* __restrict__ gs_scal4,
    const float4* __restrict__ gs_op4,
    const float*  __restrict__ feat_dc,
    const float*  __restrict__ feat_rest,
    float*        __restrict__ out,
    int N)
{
    long e = (long)blockIdx.x * blockDim.x + threadIdx.x;
    const long ns4 = 3L * N / 4;
    const long no4 = (long)N / 4;
    float4* o_s4   = (float4*)(out + 12L * N);
    float4* o_o4   = (float4*)(out + 15L * N);
    float4* o_sph4 = (float4*)(out + 16L * N);

    if (e < ns4) {
        float4 v = __ldg(&gs_scal4[e]);
        v.x = 0.1f * sigmoidf(v.x); v.y = 0.1f * sigmoidf(v.y);
        v.z = 0.1f * sigmoidf(v.z); v.w = 0.1f * sigmoidf(v.w);
        o_s4[e] = v;
    } else if (e < ns4 + no4) {
        long i = e - ns4;
        float4 v = __ldg(&gs_op4[i]);
        v.x = sigmoidf(v.x); v.y = sigmoidf(v.y);
        v.z = sigmoidf(v.z); v.w = sigmoidf(v.w);
        o_o4[i] = v;
    } else if (e < ns4 + no4 + 3L * N) {
        long s4 = e - ns4 - no4;
        int n = (int)(s4 / 3);
        int r = (int)(s4 - 3L * n);
        float4 v;
        const float* dc = feat_dc + 3 * n;
        const float* fr = feat_rest + 9 * n;
        if (r == 0) {
            v.x = __ldg(&dc[0]); v.y = __ldg(&dc[1]); v.z = __ldg(&dc[2]); v.w = __ldg(&fr[0]);
        } else if (r == 1) {
            v.x = __ldg(&fr[1]); v.y = __ldg(&fr[2]); v.z = __ldg(&fr[3]); v.w = __ldg(&fr[4]);
        } else {
            v.x = __ldg(&fr[5]); v.y = __ldg(&fr[6]); v.z = __ldg(&fr[7]); v.w = __ldg(&fr[8]);
        }
        o_sph4[s4] = v;
    }
}

extern "C" void kernel_launch(void* const* d_in, const int* in_sizes, int n_in,
                              void* d_out, int out_size) {
    const float*  gs_xyz     = (const float*)d_in[0];
    const float4* gs_rot     = (const float4*)d_in[1];
    const float4* gs_scal4   = (const float4*)d_in[2];
    const float4* gs_op4     = (const float4*)d_in[3];
    const float*  feat_dc    = (const float*)d_in[4];
    const float*  feat_rest  = (const float*)d_in[5];
    const float*  node_xyz   = (const float*)d_in[6];
    const float4* node_quat  = (const float4*)d_in[7];
    const float*  node_sigma = (const float*)d_in[8];
    const float4* node_sem4  = (const float4*)d_in[9];
    const int*    attach     = (const int*)d_in[10];
    const int*    ref_time   = (const int*)d_in[11];
    const int2*   topo2      = (const int2*)d_in[12];
    const int*    t_ptr      = (const int*)d_in[13];

    int N = in_sizes[0] / 3;

    long total4 = (3L * N) / 4 + (long)N / 4 + 3L * N;
    int eblocks = (int)((total4 + 255) / 256);
    dyn_scf_elem_kernel<<<eblocks, 256>>>(
        gs_scal4, gs_op4, feat_dc, feat_rest, (float*)d_out, N);

    int pblocks = (T_STEPS * M_NODES + 255) / 256;
    dyn_scf_pre_kernel<<<pblocks, 256>>>(node_xyz, node_quat, node_sigma, t_ptr);

    int blocks = (N + 31) / 32;
    dyn_scf_qw_kernel<<<blocks, 256>>>(
        gs_xyz, gs_rot, node_quat, node_sem4,
        attach, ref_time, topo2, (float*)d_out, N);
}

// round 11
// speedup vs baseline: 1.1170x; 1.1170x over previous
#include <cuda_runtime.h>
#include <cuda_bf16.h>

#define M_NODES 10000
#define T_STEPS 40
#define KNN     16
#define FSEM    32
#define EPSV    1e-8f

// Merged (tt,j)-indexed record: 32B aligned => a+b live in ONE 32B sector of one
// 128B line (1 L1 miss + 1 hit per neighbor instead of 2 misses; half the L2 sectors).
// a = (pref.xyz, 1/(2 sig^2+eps)); b = q_rel.
struct __align__(32) ABRec { float4 a, b; };
__device__ ABRec  g_AB[T_STEPS * M_NODES];   // 12.8 MB, L2-resident
__device__ float4 g_C[M_NODES];              // 160 KB -> L1-resident (p_live.xyz, 0)

struct Quat { float w, x, y, z; };

__device__ __forceinline__ Quat qnormalize(Quat q) {
    float n2 = q.w * q.w + q.x * q.x + q.y * q.y + q.z * q.z;
    float inv = rsqrtf(fmaxf(n2, 1e-24f));   // matches reference clip(norm,1e-12)
    Quat r; r.w = q.w * inv; r.x = q.x * inv; r.y = q.y * inv; r.z = q.z * inv;
    return r;
}

__device__ __forceinline__ Quat qload(float4 v) {
    Quat q; q.w = v.x; q.x = v.y; q.y = v.z; q.z = v.w; return q;
}

__device__ __forceinline__ Quat qmul(Quat a, Quat b) {
    Quat r;
    r.w = a.w * b.w - a.x * b.x - a.y * b.y - a.z * b.z;
    r.x = a.w * b.x + a.x * b.w + a.y * b.z - a.z * b.y;
    r.y = a.w * b.y - a.x * b.z + a.y * b.w + a.z * b.x;
    r.z = a.w * b.z + a.x * b.y - a.y * b.x + a.z * b.w;
    return r;
}

// RAW q2R (no internal normalize): for q ~ 0 yields ~I (reference degenerate path).
__device__ __forceinline__ void q2R(Quat q, float R[3][3]) {
    float w = q.w, x = q.x, y = q.y, z = q.z;
    R[0][0] = 1.f - 2.f * (y * y + z * z);
    R[0][1] = 2.f * (x * y - w * z);
    R[0][2] = 2.f * (x * z + w * y);
    R[1][0] = 2.f * (x * y + w * z);
    R[1][1] = 1.f - 2.f * (x * x + z * z);
    R[1][2] = 2.f * (y * z - w * x);
    R[2][0] = 2.f * (x * z - w * y);
    R[2][1] = 2.f * (y * z + w * x);
    R[2][2] = 1.f - 2.f * (x * x + y * y);
}

__device__ __forceinline__ void mat3mul(const float A[3][3], const float B[3][3], float C[3][3]) {
    #pragma unroll
    for (int i = 0; i < 3; i++)
        #pragma unroll
        for (int j = 0; j < 3; j++)
            C[i][j] = A[i][0] * B[0][j] + A[i][1] * B[1][j] + A[i][2] * B[2][j];
}

__device__ __forceinline__ float3 qrot(Quat q, float3 v) {
    float tx = 2.f * (q.y * v.z - q.z * v.y);
    float ty = 2.f * (q.z * v.x - q.x * v.z);
    float tz = 2.f * (q.x * v.y - q.y * v.x);
    float3 r;
    r.x = v.x + q.w * tx + (q.y * tz - q.z * ty);
    r.y = v.y + q.w * ty + (q.z * tx - q.x * tz);
    r.z = v.z + q.w * tz + (q.x * ty - q.y * tx);
    return r;
}

__device__ __forceinline__ float sigmoidf(float x) {
    return 1.f / (1.f + __expf(-x));
}

__device__ __forceinline__ float qw_sum(float v) {
    v += __shfl_xor_sync(0xffffffffu, v, 4);
    v += __shfl_xor_sync(0xffffffffu, v, 2);
    v += __shfl_xor_sync(0xffffffffu, v, 1);
    return v;
}

// ---- precompute kernel: one thread per (tt, j) ----
__global__ void __launch_bounds__(256)
dyn_scf_pre_kernel(
    const float*  __restrict__ node_xyz,
    const float4* __restrict__ node_quat,
    const float*  __restrict__ node_sigma,
    const int*    __restrict__ t_ptr)
{
    int idx = blockIdx.x * blockDim.x + threadIdx.x;
    if (idx >= T_STEPS * M_NODES) return;
    int j  = idx % M_NODES;
    int tt = idx / M_NODES;
    int t  = __ldg(t_ptr);
    long tMj = (long)t * M_NODES + j;

    Quat qr = qnormalize(qload(__ldg(&node_quat[idx])));
    Quat ql = qnormalize(qload(__ldg(&node_quat[tMj])));
    // q_rel = ql * conj(qr)
    float4 B;
    B.x =  ql.w * qr.w + ql.x * qr.x + ql.y * qr.y + ql.z * qr.z;
    B.y = -ql.w * qr.x + ql.x * qr.w - ql.y * qr.z + ql.z * qr.y;
    B.z = -ql.w * qr.y + ql.x * qr.z + ql.y * qr.w - ql.z * qr.x;
    B.w = -ql.w * qr.z - ql.x * qr.y + ql.y * qr.x + ql.z * qr.w;

    float sig = __ldg(&node_sigma[j]);
    float px = __ldg(&node_xyz[3L * idx]);
    float py = __ldg(&node_xyz[3L * idx + 1]);
    float pz = __ldg(&node_xyz[3L * idx + 2]);

    g_AB[idx].a = make_float4(px, py, pz, 1.f / (2.f * sig * sig + EPSV));
    g_AB[idx].b = B;
    if (tt == t) g_C[j] = make_float4(px, py, pz, 0.f);
}

// ---- main kernel: quarter-warp (8 lanes) per gaussian; 4 gaussians per warp ----
__global__ void __launch_bounds__(256)
dyn_scf_qw_kernel(
    const float*  __restrict__ gs_xyz,     // (N,3)
    const float4* __restrict__ gs_rot,     // (N,4)
    const float4* __restrict__ node_quat,  // (T,M,4)
    const float4* __restrict__ node_sem4,  // (M,32) as M x 8 float4
    const int*    __restrict__ attach,     // (N,)
    const int*    __restrict__ ref_time,   // (N,)
    const int2*   __restrict__ topo2,      // (M,K) as M x 8 int2
    float*        __restrict__ out,
    int N)
{
    const int lane = threadIdx.x & 31;
    const int kl   = lane & 7;
    const int grp  = (lane >> 3) & 3;
    const long warp_gid = (long)blockIdx.x * (blockDim.x >> 5) + (threadIdx.x >> 5);
    const int n = (int)(warp_gid * 4 + grp);
    if (n >= N) return;   // N % 32 == 0 -> warps never partial

    const int a  = __ldg(&attach[n]);
    const int rt = __ldg(&ref_time[n]);
    const long rtM = (long)rt * M_NODES;

    // topo: one coalesced int2 per lane covers k = 2kl, 2kl+1 (sum order irrelevant)
    const int2 jj = __ldg(&topo2[a * (KNN / 2) + kl]);
    const int j0 = jj.x, j1 = jj.y;

    // ---- k-phase gathers issued early (overlap preamble math with their latency) ----
    const ABRec* P0 = &g_AB[rtM + j0];
    const ABRec* P1 = &g_AB[rtM + j1];
    float4 A0 = __ldg(&P0->a);
    float4 A1 = __ldg(&P1->a);
    float4 B0 = __ldg(&P0->b);
    float4 B1 = __ldg(&P1->b);
    float4 C0 = __ldg(&g_C[j0]);   // 160KB table: near-always L1-hit
    float4 C1 = __ldg(&g_C[j1]);

    // ---- preamble: quaternion-only ----
    float4 Aa = __ldg(&g_AB[rtM + a].a);
    Quat qa = qnormalize(qload(__ldg(&node_quat[rtM + a])));
    Quat qg = qnormalize(qload(__ldg(&gs_rot[n])));

    float3 gx = { __ldg(&gs_xyz[3 * n]), __ldg(&gs_xyz[3 * n + 1]), __ldg(&gs_xyz[3 * n + 2]) };
    float3 xr = qrot(qa, gx);
    float3 xw = { xr.x + Aa.x, xr.y + Aa.y, xr.z + Aa.z };

    Quat qag = qmul(qa, qg);   // unit*unit -> unit; R_world = R(qag)

    float3 d0 = { xw.x - A0.x, xw.y - A0.y, xw.z - A0.z };
    float3 d1 = { xw.x - A1.x, xw.y - A1.y, xw.z - A1.z };
    float w0 = __expf(-(d0.x * d0.x + d0.y * d0.y + d0.z * d0.z) * A0.w);
    float w1 = __expf(-(d1.x * d1.x + d1.y * d1.y + d1.z * d1.z) * A1.w);

    Quat q0; q0.w = B0.x; q0.x = B0.y; q0.y = B0.z; q0.z = B0.w;
    Quat q1; q1.w = B1.x; q1.x = B1.y; q1.y = B1.z; q1.z = B1.w;
    float3 m0 = qrot(q0, d0);
    float3 m1 = qrot(q1, d1);

    // ---- group reductions (serve all 4 gaussians of the warp at once) ----
    float S   = qw_sum(w0 + w1);
    float mux = qw_sum(w0 * (m0.x + C0.x) + w1 * (m1.x + C1.x));
    float muy = qw_sum(w0 * (m0.y + C0.y) + w1 * (m1.y + C1.y));
    float muz = qw_sum(w0 * (m0.z + C0.z) + w1 * (m1.z + C1.z));
    float qbw = qw_sum(w0 * q0.w + w1 * q1.w);
    float qbx = qw_sum(w0 * q0.x + w1 * q1.x);
    float qby = qw_sum(w0 * q0.y + w1 * q1.y);
    float qbz = qw_sum(w0 * q0.z + w1 * q1.z);

    float invS = 1.f / (S + EPSV);

    // ---- sem blend (after reductions, as in the 73.5us version: shortest live ranges) ----
    const int src_base = lane & 24;
    float4 sacc = make_float4(0.f, 0.f, 0.f, 0.f);
    #pragma unroll
    for (int k = 0; k < 8; k++) {
        float wk = __shfl_sync(0xffffffffu, w0, src_base | k);
        int   jk = __shfl_sync(0xffffffffu, j0, src_base | k);
        float4 v = __ldg(&node_sem4[(long)jk * (FSEM / 4) + kl]);
        sacc.x += wk * v.x; sacc.y += wk * v.y; sacc.z += wk * v.z; sacc.w += wk * v.w;
    }
    #pragma unroll
    for (int k = 0; k < 8; k++) {
        float wk = __shfl_sync(0xffffffffu, w1, src_base | k);
        int   jk = __shfl_sync(0xffffffffu, j1, src_base | k);
        float4 v = __ldg(&node_sem4[(long)jk * (FSEM / 4) + kl]);
        sacc.x += wk * v.x; sacc.y += wk * v.y; sacc.z += wk * v.z; sacc.w += wk * v.w;
    }

    // ---- frame epilogue: EXPLICIT Rb @ Rw (clip-safe; see R8 failure).
    // invS scaling BEFORE normalize is load-bearing (R2 failure): for clipped rows
    // qbn ~ 0 -> Rb ~ I -> Fr = Rw, which quaternion composition would NOT give.
    Quat qbn; qbn.w = qbw * invS; qbn.x = qbx * invS; qbn.y = qby * invS; qbn.z = qbz * invS;
    qbn = qnormalize(qbn);
    float Rb[3][3]; q2R(qbn, Rb);
    float Rw[3][3]; q2R(qag, Rw);
    float Fr[3][3]; mat3mul(Rb, Rw, Fr);

    // ---- outputs ----
    float*  o_mu  = out;
    float*  o_fr  = out + 3L  * N;
    float4* o_sem = (float4*)(out + 28L * N);

    float muv = (kl == 0) ? mux : ((kl == 1) ? muy : muz);
    if (kl < 3) o_mu[3 * n + kl] = muv * invS;

    float frv = Fr[0][0];
    frv = (kl == 1) ? Fr[0][1] : frv;
    frv = (kl == 2) ? Fr[0][2] : frv;
    frv = (kl == 3) ? Fr[1][0] : frv;
    frv = (kl == 4) ? Fr[1][1] : frv;
    frv = (kl == 5) ? Fr[1][2] : frv;
    frv = (kl == 6) ? Fr[2][0] : frv;
    frv = (kl == 7) ? Fr[2][1] : frv;
    o_fr[9 * n + kl] = frv;
    if (kl == 0) o_fr[9 * n + 8] = Fr[2][2];

    float4 sv; sv.x = sacc.x * invS; sv.y = sacc.y * invS;
    sv.z = sacc.z * invS; sv.w = sacc.w * invS;
    o_sem[(long)n * (FSEM / 4) + kl] = sv;
}

// ---- elementwise outputs: s, o, sph — float4 vectorized ----
__global__ void __launch_bounds__(256)
dyn_scf_elem_kernel(
    const float4* __restrict__ gs_scal4,
    const float4* __restrict__ gs_op4,
    const float*  __restrict__ feat_dc,
    const float*  __restrict__ feat_rest,
    float*        __restrict__ out,
    int N)
{
    long e = (long)blockIdx.x * blockDim.x + threadIdx.x;
    const long ns4 = 3L * N / 4;
    const long no4 = (long)N / 4;
    float4* o_s4   = (float4*)(out + 12L * N);
    float4* o_o4   = (float4*)(out + 15L * N);
    float4* o_sph4 = (float4*)(out + 16L * N);

    if (e < ns4) {
        float4 v = __ldg(&gs_scal4[e]);
        v.x = 0.1f * sigmoidf(v.x); v.y = 0.1f * sigmoidf(v.y);
        v.z = 0.1f * sigmoidf(v.z); v.w = 0.1f * sigmoidf(v.w);
        o_s4[e] = v;
    } else if (e < ns4 + no4) {
        long i = e - ns4;
        float4 v = __ldg(&gs_op4[i]);
        v.x = sigmoidf(v.x); v.y = sigmoidf(v.y);
        v.z = sigmoidf(v.z); v.w = sigmoidf(v.w);
        o_o4[i] = v;
    } else if (e < ns4 + no4 + 3L * N) {
        long s4 = e - ns4 - no4;
        int n = (int)(s4 / 3);
        int r = (int)(s4 - 3L * n);
        float4 v;
        const float* dc = feat_dc + 3 * n;
        const float* fr = feat_rest + 9 * n;
        if (r == 0) {
            v.x = __ldg(&dc[0]); v.y = __ldg(&dc[1]); v.z = __ldg(&dc[2]); v.w = __ldg(&fr[0]);
        } else if (r == 1) {
            v.x = __ldg(&fr[1]); v.y = __ldg(&fr[2]); v.z = __ldg(&fr[3]); v.w = __ldg(&fr[4]);
        } else {
            v.x = __ldg(&fr[5]); v.y = __ldg(&fr[6]); v.z = __ldg(&fr[7]); v.w = __ldg(&fr[8]);
        }
        o_sph4[s4] = v;
    }
}

extern "C" void kernel_launch(void* const* d_in, const int* in_sizes, int n_in,
                              void* d_out, int out_size) {
    const float*  gs_xyz     = (const float*)d_in[0];
    const float4* gs_rot     = (const float4*)d_in[1];
    const float4* gs_scal4   = (const float4*)d_in[2];
    const float4* gs_op4     = (const float4*)d_in[3];
    const float*  feat_dc    = (const float*)d_in[4];
    const float*  feat_rest  = (const float*)d_in[5];
    const float*  node_xyz   = (const float*)d_in[6];
    const float4* node_quat  = (const float4*)d_in[7];
    const float*  node_sigma = (const float*)d_in[8];
    const float4* node_sem4  = (const float4*)d_in[9];
    const int*    attach     = (const int*)d_in[10];
    const int*    ref_time   = (const int*)d_in[11];
    const int2*   topo2      = (const int2*)d_in[12];
    const int*    t_ptr      = (const int*)d_in[13];

    int N = in_sizes[0] / 3;

    long total4 = (3L * N) / 4 + (long)N / 4 + 3L * N;
    int eblocks = (int)((total4 + 255) / 256);
    dyn_scf_elem_kernel<<<eblocks, 256>>>(
        gs_scal4, gs_op4, feat_dc, feat_rest, (float*)d_out, N);

    int pblocks = (T_STEPS * M_NODES + 255) / 256;
    dyn_scf_pre_kernel<<<pblocks, 256>>>(node_xyz, node_quat, node_sigma, t_ptr);

    int blocks = (N + 31) / 32;
    dyn_scf_qw_kernel<<<blocks, 256>>>(
        gs_xyz, gs_rot, node_quat, node_sem4,
        attach, ref_time, topo2, (float*)d_out, N);
}